// round 13
// baseline (speedup 1.0000x reference)
#include <cuda_runtime.h>
#include <math.h>

#define BATCH 8
#define NA 147456
#define PRE 2000
#define POST 300
#define NBIN 4096
#define SLOTS 2048
#define CAP512 1024
#define NSLICE 4
#define NMS_THR 0.7f
#define IMG 1024.0f
#define ABASE 16.0f
#define FULL 0xffffffffu

// ---------------- scratch (zero-init at load; kernels restore invariants) ---
__device__ unsigned int       g_hist[BATCH][NBIN];
__device__ unsigned char      g_validb[BATCH][NA / 4];
__device__ int                g_thr512[BATCH];
__device__ int                g_thresh[BATCH];
__device__ int                g_c512[BATCH];
__device__ int                g_count[BATCH];
__device__ int                g_K[BATCH];      // min(PRE, cnt@thr2000)
__device__ int                g_K512[BATCH];   // raw count @thr512
__device__ int                g_done[BATCH];
__device__ int                g_rank[BATCH][CAP512];
__device__ int                g_harrive;
__device__ int                g_rarrive[BATCH];
__device__ int                g_marrive[BATCH];
__device__ unsigned long long g_key512[BATCH][CAP512];
__device__ unsigned long long g_ckey[BATCH][SLOTS];
__device__ float4             g_box[BATCH][SLOTS];
__device__ float              g_sscore[BATCH][SLOTS];
__device__ unsigned long long g_mask512[BATCH][512][8];
__device__ unsigned long long g_mask[BATCH][PRE][32];

// ---------------- exact decode (fp64 exp — reference decision path) ---------
__device__ __forceinline__ void decode_box(float4 a, float4 r,
                                           float4& box, bool& valid) {
    float ah  = a.z - a.x;
    float aw  = a.w - a.y;
    float acy = a.x + 0.5f * ah;
    float acx = a.y + 0.5f * aw;
    float cy  = r.x * ah + acy;
    float cx  = r.y * aw + acx;
    float hh  = (float)exp((double)r.z) * ah;
    float ww  = (float)exp((double)r.w) * aw;
    float y1 = fminf(fmaxf(cy - 0.5f * hh, 0.0f), IMG);
    float x1 = fminf(fmaxf(cx - 0.5f * ww, 0.0f), IMG);
    float y2 = fminf(fmaxf(cy + 0.5f * hh, 0.0f), IMG);
    float x2 = fminf(fmaxf(cx + 0.5f * ww, 0.0f), IMG);
    box = make_float4(y1, x1, y2, x2);
    valid = ((y2 - y1) >= ABASE) && ((x2 - x1) >= ABASE);
}

// fast validity: fp32 __expf with margin; falls back to exact fp64 on boundary
__device__ __forceinline__ bool decode_valid_fast(float4 a, float4 r) {
    float ah  = a.z - a.x;
    float aw  = a.w - a.y;
    float acy = a.x + 0.5f * ah;
    float acx = a.y + 0.5f * aw;
    float cy  = r.x * ah + acy;
    float cx  = r.y * aw + acx;
    float hh  = __expf(r.z) * ah;
    float ww  = __expf(r.w) * aw;
    float y1 = fminf(fmaxf(cy - 0.5f * hh, 0.0f), IMG);
    float x1 = fminf(fmaxf(cx - 0.5f * ww, 0.0f), IMG);
    float y2 = fminf(fmaxf(cy + 0.5f * hh, 0.0f), IMG);
    float x2 = fminf(fmaxf(cx + 0.5f * ww, 0.0f), IMG);
    float dh = (y2 - y1) - ABASE;
    float dw = (x2 - x1) - ABASE;
    float mh = 1e-3f + 1e-5f * fabsf(hh);   // >> worst fast-vs-exact divergence
    float mw = 1e-3f + 1e-5f * fabsf(ww);
    if (fabsf(dh) >= mh && fabsf(dw) >= mw)
        return (dh > 0.0f) && (dw > 0.0f);
    float4 box; bool valid;                 // boundary: exact path
    decode_box(a, r, box, valid);
    return valid;
}

__device__ __forceinline__ int score_bin(float s) {
    int b = (int)(s * 4096.0f);
    return b > 4095 ? 4095 : (b < 0 ? 0 : b);
}

__device__ __forceinline__ unsigned warp_suffix(unsigned v, int lane) {
    unsigned r = v;
#pragma unroll
    for (int off = 1; off < 32; off <<= 1) {
        unsigned t = __shfl_down_sync(FULL, r, off);
        if (lane < 32 - off) r += t;        // suffix sum lane..31
    }
    return r;
}

__device__ __forceinline__ unsigned long long ldcg64(const unsigned long long* p) {
    return __ldcg((const unsigned long long*)p);
}

// ---------------- K1: validity + histogram; LAST BLOCK: thresholds + init ---
__global__ void __launch_bounds__(256) k_hist(const float* __restrict__ anchor,
                       const float* __restrict__ reg,
                       const float* __restrict__ score, float* out) {
    __shared__ unsigned int sh[NBIN];
    __shared__ int slast;
    int b = blockIdx.y;
    for (int i = threadIdx.x; i < NBIN; i += 256) sh[i] = 0;
    __syncthreads();
    const float4* A = (const float4*)anchor + (size_t)b * NA;
    const float4* R = (const float4*)reg + (size_t)b * NA;
    int tid4 = blockIdx.x * 256 + threadIdx.x;  // 144*256 == NA/4 exactly
    float4 s4 = ((const float4*)(score + (size_t)b * NA))[tid4];
    float4 a[4], r[4];
#pragma unroll
    for (int k = 0; k < 4; k++) {               // 9 LDG.128 issued up front
        a[k] = A[tid4 * 4 + k];
        r[k] = R[tid4 * 4 + k];
    }
    unsigned bits = 0;
#pragma unroll
    for (int k = 0; k < 4; k++)
        if (decode_valid_fast(a[k], r[k])) bits |= 1u << k;
    g_validb[b][tid4] = (unsigned char)bits;
    float sv[4] = {s4.x, s4.y, s4.z, s4.w};
#pragma unroll
    for (int k = 0; k < 4; k++)
        if ((bits >> k) & 1u) atomicAdd(&sh[score_bin(sv[k])], 1u);
    __syncthreads();
    for (int i = threadIdx.x; i < NBIN; i += 256)
        if (sh[i]) atomicAdd(&g_hist[b][i], sh[i]);

    // ---- grid arrival; last block computes thresholds + output init ----
    __threadfence();
    __syncthreads();
    if (threadIdx.x == 0)
        slast = (atomicAdd(&g_harrive, 1) == 144 * BATCH - 1) ? 1 : 0;
    __syncthreads();
    if (!slast) return;
    if (threadIdx.x == 0) g_harrive = 0;        // restore invariant

    int lane = threadIdx.x & 31;
    int bb = threadIdx.x >> 5;                  // 8 warps, one per batch
    unsigned acc = 0, cnt2000 = 0;
    int t512 = 0, t2000 = 0;
    bool f512 = false, f2000 = false;
    unsigned v[4], vn[4];
#pragma unroll
    for (int u = 0; u < 4; u++)
        v[u] = __ldcg(&g_hist[bb][(127 - u) * 32 + lane]);
    for (int g = 0; g < 32 && !f2000; g++) {
        int nbase = 127 - (g + 1) * 4;
#pragma unroll
        for (int u = 0; u < 4; u++)
            vn[u] = (nbase - u >= 0) ? __ldcg(&g_hist[bb][(nbase - u) * 32 + lane]) : 0u;
#pragma unroll
        for (int u = 0; u < 4; u++) {
            if (f2000) break;
            int s = 127 - g * 4 - u;
            unsigned tot = __reduce_add_sync(FULL, v[u]);
            if (!f512 && acc + tot >= 512) {
                unsigned rr = warp_suffix(v[u], lane);
                unsigned bal = __ballot_sync(FULL, acc + rr >= 512);
                t512 = s * 32 + (31 - __clz(bal));
                f512 = true;
            }
            if (acc + tot >= PRE) {
                unsigned rr = warp_suffix(v[u], lane);
                unsigned bal = __ballot_sync(FULL, acc + rr >= PRE);
                int L = 31 - __clz(bal);
                t2000 = s * 32 + L;
                cnt2000 = acc + __shfl_sync(FULL, rr, L);
                f2000 = true;
            }
            acc += tot;
        }
#pragma unroll
        for (int u = 0; u < 4; u++) v[u] = vn[u];
    }
    if (!f2000) cnt2000 = acc;                  // fewer than PRE valid total
    if (lane == 0) {
        g_thr512[bb] = t512;
        g_thresh[bb] = t2000;
        g_K[bb] = cnt2000 < PRE ? (int)cnt2000 : PRE;
    }
    // output init: zero boxes+scores, batch indices
    for (int t = threadIdx.x; t < BATCH * POST * 5; t += 256) out[t] = 0.0f;
    for (int t = threadIdx.x; t < BATCH * POST; t += 256)
        out[BATCH * POST * 5 + t] = (float)(t / POST);
}

// ---------------- warp-aggregated append ----------------
__device__ __forceinline__ void wappend(bool cand, unsigned long long key,
                                        int* counter,
                                        unsigned long long* buf, int cap,
                                        int lane) {
    unsigned ballot = __ballot_sync(FULL, cand);
    if (cand) {
        int leader = __ffs(ballot) - 1;
        int rank = __popc(ballot & ((1u << lane) - 1u));
        int pos = 0;
        if (lane == leader) pos = atomicAdd(counter, __popc(ballot));
        pos = __shfl_sync(ballot, pos, leader) + rank;
        if (pos < cap) buf[pos] = key;
    }
}

// ---------------- K2: 4-wide gather of both lists + hist clear --------------
__global__ void __launch_bounds__(256) k_gather(const float* __restrict__ score) {
    int b = blockIdx.y;
    if (blockIdx.x < 16)                        // 16*256 == NBIN
        g_hist[b][blockIdx.x * 256 + threadIdx.x] = 0u;
    int tid4 = blockIdx.x * 256 + threadIdx.x;  // 144*256 == NA/4
    int lane = threadIdx.x & 31;
    float4 s4 = ((const float4*)(score + (size_t)b * NA))[tid4];
    unsigned vb = g_validb[b][tid4];
    int thr2000 = g_thresh[b], thr512 = g_thr512[b];
    float sv[4] = {s4.x, s4.y, s4.z, s4.w};
#pragma unroll
    for (int k = 0; k < 4; k++) {
        int i = tid4 * 4 + k;
        bool valid = (vb >> k) & 1u;
        int bin = score_bin(sv[k]);
        unsigned u = __float_as_uint(sv[k]) | 0x80000000u;   // s >= 0
        unsigned long long key = ((unsigned long long)u << 32) | (unsigned)(~i);
        wappend(valid && bin >= thr2000, key, &g_count[b], g_ckey[b], SLOTS, lane);
        wappend(valid && bin >= thr512,  key, &g_c512[b], g_key512[b], CAP512, lane);
    }
}

// ---------------- K3: sliced rank-sort; LAST BLOCK: scatter + decode --------
__global__ void __launch_bounds__(512) k_rank512(const float* __restrict__ anchor,
                          const float* __restrict__ reg) {
    __shared__ unsigned long long slice[(CAP512 + NSLICE - 1) / NSLICE];
    __shared__ unsigned long long sorted[512];
    __shared__ int slast;
    int b = blockIdx.y, q = blockIdx.x;
    int t = threadIdx.x;                        // 512 threads
    int Craw = g_c512[b];
    int C = Craw > CAP512 ? CAP512 : Craw;
    int Cq = (C + NSLICE - 1) / NSLICE;
    int j0 = q * Cq;
    int j1 = j0 + Cq; if (j1 > C) j1 = C;
    int ns = j1 - j0; if (ns < 0) ns = 0;
    if (t < ns) slice[t] = g_key512[b][j0 + t];
    __syncthreads();
#pragma unroll
    for (int e = 0; e < 2; e++) {               // partial rank over this slice
        int i = t + e * 512;
        if (i < C) {
            unsigned long long ki = g_key512[b][i];
            int cnt = 0;
            int j = 0;
            for (; j + 8 <= ns; j += 8) {
#pragma unroll
                for (int u = 0; u < 8; u++) cnt += (slice[j + u] > ki);
            }
            for (; j < ns; j++) cnt += (slice[j] > ki);
            atomicAdd(&g_rank[b][i], cnt);
        }
    }
    __threadfence();
    __syncthreads();
    if (t == 0) slast = (atomicAdd(&g_rarrive[b], 1) == NSLICE - 1) ? 1 : 0;
    __syncthreads();
    if (!slast) return;
    // ---- last slice block: scatter to sorted order, reset, decode ----
#pragma unroll
    for (int e = 0; e < 2; e++) {
        int i = t + e * 512;
        if (i < C) {
            int r = __ldcg(&g_rank[b][i]);
            if (r < 512) sorted[r] = ldcg64(&g_key512[b][i]);
            g_rank[b][i] = 0;                   // restore invariant
        } else if (i < CAP512) g_rank[b][i] = 0;
    }
    if (t == 0) { g_rarrive[b] = 0; g_c512[b] = 0; g_K512[b] = Craw; }
    __syncthreads();
    int K5 = C < 512 ? C : 512;
    float4 bx = make_float4(0.f, 0.f, 0.f, 0.f);
    float sc = 0.f;
    if (t < K5) {                               // exact fp64 decode, winners only
        unsigned long long key = sorted[t];
        int i = ~((unsigned)key);
        const float4* A = (const float4*)anchor + (size_t)b * NA;
        const float4* R = (const float4*)reg + (size_t)b * NA;
        bool valid;
        decode_box(A[i], R[i], bx, valid);
        sc = __uint_as_float(((unsigned)(key >> 32)) & 0x7fffffffu);
    }
    g_box[b][t] = bx;
    g_sscore[b][t] = sc;
}

// ---------------- shared IoU test ----------------
__device__ __forceinline__ bool iou_over(float4 ib, float ia, float4 jb) {
    float ty = fmaxf(ib.x, jb.x);
    float by = fminf(ib.z, jb.z);
    float lx = fmaxf(ib.y, jb.y);
    float rx = fminf(ib.w, jb.w);
    float inter = fmaxf(by - ty, 0.f) * fmaxf(rx - lx, 0.f);
    float ja = (jb.z - jb.x) * (jb.w - jb.y);
    // prefilter: iou>0.7 => 1.7*inter > 0.7*(ia+ja); 2e-4 margin
    if (inter * 1.7002f > 0.69993f * (ia + ja)) {
        float iou = inter / (ia + ja - inter + 1e-9f);   // exact IEEE
        return iou > NMS_THR;
    }
    return false;
}

// ---------------- K4: 512-mask (128 blocks); LAST BLOCK/batch: scan + emit --
__global__ void __launch_bounds__(256) k_mask512(float* out) {
    __shared__ int slast;
    int b = blockIdx.y;
    int bi = blockIdx.x;                        // 16 blocks of 32 i's
    int lane = threadIdx.x & 31;
    int w = threadIdx.x >> 5;                   // 8 warps = words 0..7
    int i = bi * 32 + lane;                     // < 512
    float4 ib = g_box[b][i];
    float ia = (ib.z - ib.x) * (ib.w - ib.y);
    if (w * 64 + 63 <= bi * 32) {               // whole word below diagonal
        g_mask512[b][i][w] = 0ULL;
    } else {
        unsigned long long bits = 0ULL;
        for (int k = 0; k < 64; k++) {
            int j = w * 64 + k;                 // warp-uniform j, < 512
            float4 jb = __ldg(&g_box[b][j]);
            if (j > i && iou_over(ib, ia, jb)) bits |= (1ULL << k);
        }
        g_mask512[b][i][w] = bits;
    }
    __threadfence();
    __syncthreads();
    if (threadIdx.x == 0)
        slast = (atomicAdd(&g_marrive[b], 1) == 15) ? 1 : 0;
    __syncthreads();
    if (!slast) return;
    if (threadIdx.x == 0) g_marrive[b] = 0;     // restore invariant
    if (threadIdx.x >= 32) return;
    // ---- warp 0: greedy scan over 512 prefix; emit if decisive ----
    {
        int Kb = g_K[b];
        int Craw = g_K512[b];
        int C = Craw > CAP512 ? CAP512 : Craw;
        int K5 = C < 512 ? C : 512;

        unsigned long long removed;
        if (lane < 8) {
            int lo = lane * 64;
            if (K5 <= lo) removed = ~0ULL;
            else if (K5 >= lo + 64) removed = 0ULL;
            else removed = (~0ULL) << (K5 - lo);
        } else removed = ~0ULL;

        unsigned long long cur[16], nxt[16];
#pragma unroll
        for (int d = 0; d < 16; d++)
            cur[d] = (lane < 8 && d < K5) ? ldcg64(&g_mask512[b][d][lane]) : 0ULL;

        for (int ibase = 0; ibase < 512; ibase += 16) {
            if (ibase >= K5) break;
#pragma unroll
            for (int d = 0; d < 16; d++) {
                int pf = ibase + 16 + d;
                nxt[d] = (lane < 8 && pf < K5) ? ldcg64(&g_mask512[b][pf][lane]) : 0ULL;
            }
            int ww = ibase >> 6;                // uniform (16 | 64), < 8
            unsigned dec = 0;
            if (lane == ww) {
                unsigned long long rw = removed;
#pragma unroll
                for (int d = 0; d < 16; d++) {
                    int ii = ibase + d;
                    if (ii < K5 && !((rw >> (ii & 63)) & 1ULL)) {
                        dec |= 1u << d;
                        rw |= cur[d];
                    }
                }
            }
            dec = __shfl_sync(FULL, dec, ww);
#pragma unroll
            for (int d = 0; d < 16; d++)
                if (dec & (1u << d)) removed |= cur[d];
#pragma unroll
            for (int d = 0; d < 16; d++) cur[d] = nxt[d];
        }

        unsigned long long kept = ~removed;     // lanes>=8 contribute 0
        int cnt = __popcll(kept);
        int total = cnt;
#pragma unroll
        for (int off = 16; off >= 1; off >>= 1)
            total += __shfl_xor_sync(FULL, total, off);

        bool done = ((total >= POST) || (Kb <= 512)) && (Craw <= CAP512);
        if (lane == 0) g_done[b] = done ? 1 : 0;
        if (!done) return;

        int incl = cnt;
#pragma unroll
        for (int off = 1; off < 32; off <<= 1) {
            int v = __shfl_up_sync(FULL, incl, off);
            if (lane >= off) incl += v;
        }
        int base = incl - cnt;

        unsigned long long m = kept;
        while (m) {
            int tt = __ffsll(m) - 1;
            m &= m - 1ULL;
            if (base < POST) {
                int slot = lane * 64 + tt;      // < 512
                *(float4*)(out + ((size_t)b * POST + base) * 4) = g_box[b][slot];
                out[BATCH * POST * 4 + b * POST + base] = g_sscore[b][slot];
            }
            base++;
        }
    }
}

// ---------------- K5: full fallback (sort+mask+scan in-block, gated) --------
// __launch_bounds__(1024, 1) caps regs at 64/thread so the launch always
// fits; the scan phase may spill to local — acceptable on this cold path.
__global__ void __launch_bounds__(1024, 1) k_fallback(
                           const float* __restrict__ anchor,
                           const float* __restrict__ reg, float* out) {
    __shared__ unsigned long long kk[SLOTS];    // 16 KB
    int b = blockIdx.x;
    int tid = threadIdx.x;                      // 1024 threads
    int C = g_count[b];
    __syncthreads();                            // all reads before reset
    if (tid == 0) g_count[b] = 0;               // restore invariant ALWAYS
    if (g_done[b]) return;                      // prefix path already emitted
    if (C > SLOTS) C = SLOTS;
#pragma unroll
    for (int e = 0; e < 2; e++) {
        int i = e * 1024 + tid;
        kk[i] = (i < C) ? g_ckey[b][i] : 0ULL;  // real keys have top bit set
    }
    for (int k = 2; k <= SLOTS; k <<= 1) {
        for (int j = k >> 1; j > 0; j >>= 1) {
            __syncthreads();
#pragma unroll
            for (int e = 0; e < 2; e++) {
                int i = e * 1024 + tid;
                int ixj = i ^ j;
                if (ixj > i) {
                    unsigned long long a = kk[i], c = kk[ixj];
                    bool sw = ((i & k) == 0) ? (a < c) : (a > c);
                    if (sw) { kk[i] = c; kk[ixj] = a; }
                }
            }
        }
    }
    __syncthreads();
    int Kb = (C < PRE) ? C : PRE;
    const float4* A = (const float4*)anchor + (size_t)b * NA;
    const float4* R = (const float4*)reg + (size_t)b * NA;
#pragma unroll
    for (int e = 0; e < 2; e++) {
        int p = e * 1024 + tid;
        float4 bx = make_float4(0.f, 0.f, 0.f, 0.f);
        float sc = 0.f;
        if (p < Kb) {
            unsigned long long key = kk[p];
            int i = ~((unsigned)key);
            bool valid;
            decode_box(A[i], R[i], bx, valid);
            sc = __uint_as_float(((unsigned)(key >> 32)) & 0x7fffffffu);
        }
        g_box[b][p] = bx;
        g_sscore[b][p] = sc;
    }
    __syncthreads();                            // g_box visible block-wide
    // full 2000x2048 suppression mask (slow; correctness-only path)
    for (int idx = tid; idx < PRE * 32; idx += 1024) {
        int i = idx >> 5, w = idx & 31;
        if (i >= Kb) continue;                  // rows >= Kb never read
        if (w * 64 + 63 <= i) continue;         // stays 0 (never written by anyone)
        float4 ib = g_box[b][i];
        float ia = (ib.z - ib.x) * (ib.w - ib.y);
        unsigned long long bits = 0ULL;
        for (int k = 0; k < 64; k++) {
            int j = w * 64 + k;
            float4 jb = g_box[b][j];
            if (j > i && iou_over(ib, ia, jb)) bits |= (1ULL << k);
        }
        g_mask[b][i][w] = bits;
    }
    __syncthreads();                            // mask visible block-wide
    if (tid >= 32) return;
    // warp 0: full greedy scan + emit
    int lane = tid;
    unsigned long long removed;
    {
        int lo = lane * 64;
        if (Kb <= lo) removed = ~0ULL;
        else if (Kb >= lo + 64) removed = 0ULL;
        else removed = (~0ULL) << (Kb - lo);
    }
    unsigned long long cur[16], nxt[16];
#pragma unroll
    for (int d = 0; d < 16; d++) cur[d] = (d < Kb) ? g_mask[b][d][lane] : 0ULL;
    for (int ibase = 0; ibase < PRE; ibase += 16) {
        if (ibase >= Kb) break;
#pragma unroll
        for (int d = 0; d < 16; d++) {
            int pf = ibase + 16 + d;
            nxt[d] = (pf < Kb) ? g_mask[b][pf][lane] : 0ULL;
        }
        int w = ibase >> 6;                     // uniform (16 | 64)
        unsigned dec = 0;
        if (lane == w) {
            unsigned long long rw = removed;
#pragma unroll
            for (int d = 0; d < 16; d++) {
                int i = ibase + d;
                if (i < Kb && !((rw >> (i & 63)) & 1ULL)) {
                    dec |= 1u << d;
                    rw |= cur[d];
                }
            }
        }
        dec = __shfl_sync(FULL, dec, w);
#pragma unroll
        for (int d = 0; d < 16; d++)
            if (dec & (1u << d)) removed |= cur[d];
#pragma unroll
        for (int d = 0; d < 16; d++) cur[d] = nxt[d];
    }
    unsigned long long kept = ~removed;
    int cnt = __popcll(kept);
    int incl = cnt;
#pragma unroll
    for (int off = 1; off < 32; off <<= 1) {
        int v = __shfl_up_sync(FULL, incl, off);
        if (lane >= off) incl += v;
    }
    int base = incl - cnt;
    unsigned long long m = kept;
    while (m) {
        int t = __ffsll(m) - 1;
        m &= m - 1ULL;
        if (base < POST) {
            int slot = lane * 64 + t;
            *(float4*)(out + ((size_t)b * POST + base) * 4) = g_box[b][slot];
            out[BATCH * POST * 4 + b * POST + base] = g_sscore[b][slot];
        }
        base++;
    }
}

// ---------------- launch ----------------
extern "C" void kernel_launch(void* const* d_in, const int* in_sizes, int n_in,
                              void* d_out, int out_size) {
    const float* anchor = (const float*)d_in[0];
    const float* breg   = (const float*)d_in[1];
    const float* score  = (const float*)d_in[2];
    float* out = (float*)d_out;

    k_hist<<<dim3(144, BATCH), 256>>>(anchor, breg, score, out);
    k_gather<<<dim3(144, BATCH), 256>>>(score);
    k_rank512<<<dim3(NSLICE, BATCH), 512>>>(anchor, breg);
    k_mask512<<<dim3(16, BATCH), 256>>>(out);
    k_fallback<<<BATCH, 1024>>>(anchor, breg, out);
}

// round 14
// speedup vs baseline: 1.1386x; 1.1386x over previous
#include <cuda_runtime.h>
#include <math.h>

#define BATCH 8
#define NA 147456
#define PRE 2000
#define POST 300
#define NBIN 4096
#define SLOTS 2048
#define CAP512 1024
#define NMS_THR 0.7f
#define IMG 1024.0f
#define ABASE 16.0f
#define FULL 0xffffffffu

// ---------------- scratch (zero-init at load; kernels restore invariants) ---
__device__ unsigned int       g_hist[BATCH][NBIN];
__device__ unsigned char      g_validb[BATCH][NA / 4];
__device__ int                g_thr512[BATCH];
__device__ int                g_thresh[BATCH];
__device__ int                g_c512[BATCH];
__device__ int                g_count[BATCH];
__device__ int                g_K[BATCH];      // min(PRE, cnt@thr2000)
__device__ int                g_K512[BATCH];   // raw count @thr512
__device__ int                g_done[BATCH];
__device__ unsigned long long g_key512[BATCH][CAP512];
__device__ unsigned long long g_ckey[BATCH][SLOTS];
__device__ float4             g_box[BATCH][SLOTS];
__device__ float              g_sscore[BATCH][SLOTS];
__device__ unsigned long long g_mask512[BATCH][512][8];
__device__ unsigned long long g_mask[BATCH][PRE][32];

// ---------------- exact decode (fp64 exp — reference decision path) ---------
__device__ __forceinline__ void decode_box(float4 a, float4 r,
                                           float4& box, bool& valid) {
    float ah  = a.z - a.x;
    float aw  = a.w - a.y;
    float acy = a.x + 0.5f * ah;
    float acx = a.y + 0.5f * aw;
    float cy  = r.x * ah + acy;
    float cx  = r.y * aw + acx;
    float hh  = (float)exp((double)r.z) * ah;
    float ww  = (float)exp((double)r.w) * aw;
    float y1 = fminf(fmaxf(cy - 0.5f * hh, 0.0f), IMG);
    float x1 = fminf(fmaxf(cx - 0.5f * ww, 0.0f), IMG);
    float y2 = fminf(fmaxf(cy + 0.5f * hh, 0.0f), IMG);
    float x2 = fminf(fmaxf(cx + 0.5f * ww, 0.0f), IMG);
    box = make_float4(y1, x1, y2, x2);
    valid = ((y2 - y1) >= ABASE) && ((x2 - x1) >= ABASE);
}

// fast validity: fp32 __expf with margin; falls back to exact fp64 on boundary
__device__ __forceinline__ bool decode_valid_fast(float4 a, float4 r) {
    float ah  = a.z - a.x;
    float aw  = a.w - a.y;
    float acy = a.x + 0.5f * ah;
    float acx = a.y + 0.5f * aw;
    float cy  = r.x * ah + acy;
    float cx  = r.y * aw + acx;
    float hh  = __expf(r.z) * ah;
    float ww  = __expf(r.w) * aw;
    float y1 = fminf(fmaxf(cy - 0.5f * hh, 0.0f), IMG);
    float x1 = fminf(fmaxf(cx - 0.5f * ww, 0.0f), IMG);
    float y2 = fminf(fmaxf(cy + 0.5f * hh, 0.0f), IMG);
    float x2 = fminf(fmaxf(cx + 0.5f * ww, 0.0f), IMG);
    float dh = (y2 - y1) - ABASE;
    float dw = (x2 - x1) - ABASE;
    float mh = 1e-3f + 1e-5f * fabsf(hh);   // >> worst fast-vs-exact divergence
    float mw = 1e-3f + 1e-5f * fabsf(ww);
    if (fabsf(dh) >= mh && fabsf(dw) >= mw)
        return (dh > 0.0f) && (dw > 0.0f);
    float4 box; bool valid;                 // boundary: exact path
    decode_box(a, r, box, valid);
    return valid;
}

__device__ __forceinline__ int score_bin(float s) {
    int b = (int)(s * 4096.0f);
    return b > 4095 ? 4095 : (b < 0 ? 0 : b);
}

// ---------------- K1: 4-wide validity bytes + histogram ---------------------
__global__ void __launch_bounds__(256) k_hist(const float* __restrict__ anchor,
                       const float* __restrict__ reg,
                       const float* __restrict__ score) {
    __shared__ unsigned int sh[NBIN];
    int b = blockIdx.y;
    for (int i = threadIdx.x; i < NBIN; i += 256) sh[i] = 0;
    __syncthreads();
    const float4* A = (const float4*)anchor + (size_t)b * NA;
    const float4* R = (const float4*)reg + (size_t)b * NA;
    int tid4 = blockIdx.x * 256 + threadIdx.x;  // 144*256 == NA/4 exactly
    float4 s4 = ((const float4*)(score + (size_t)b * NA))[tid4];
    float4 a[4], r[4];
#pragma unroll
    for (int k = 0; k < 4; k++) {               // 9 LDG.128 issued up front
        a[k] = A[tid4 * 4 + k];
        r[k] = R[tid4 * 4 + k];
    }
    unsigned bits = 0;
#pragma unroll
    for (int k = 0; k < 4; k++)
        if (decode_valid_fast(a[k], r[k])) bits |= 1u << k;
    g_validb[b][tid4] = (unsigned char)bits;
    float sv[4] = {s4.x, s4.y, s4.z, s4.w};
#pragma unroll
    for (int k = 0; k < 4; k++)
        if ((bits >> k) & 1u) atomicAdd(&sh[score_bin(sv[k])], 1u);
    __syncthreads();
    for (int i = threadIdx.x; i < NBIN; i += 256)
        if (sh[i]) atomicAdd(&g_hist[b][i], sh[i]);
}

// ---------------- K2: two thresholds (warp/batch) + output init -------------
__global__ void __launch_bounds__(256) k_thresh(float* out) {
    int lane = threadIdx.x & 31;
    int b = threadIdx.x >> 5;                   // 8 warps, one per batch
    unsigned acc = 0, cnt2000 = 0;
    int t512 = 0, t2000 = 0;
    bool f512 = false, f2000 = false;
    for (int s = 127; s >= 0 && !f2000; --s) {
        unsigned r = g_hist[b][s * 32 + lane];
#pragma unroll
        for (int off = 1; off < 32; off <<= 1) {
            unsigned t = __shfl_down_sync(FULL, r, off);
            if (lane < 32 - off) r += t;        // suffix sum within strip
        }
        unsigned tot = __shfl_sync(FULL, r, 0);
        if (!f512 && acc + tot >= 512) {
            unsigned bal = __ballot_sync(FULL, acc + r >= 512);
            t512 = s * 32 + (31 - __clz(bal));
            f512 = true;
        }
        if (acc + tot >= PRE) {
            unsigned bal = __ballot_sync(FULL, acc + r >= PRE);
            int L = 31 - __clz(bal);
            t2000 = s * 32 + L;
            cnt2000 = acc + __shfl_sync(FULL, r, L);
            f2000 = true;
        }
        acc += tot;
    }
    if (!f2000) cnt2000 = acc;                  // fewer than PRE valid total
    if (lane == 0) {
        g_thr512[b] = t512;
        g_thresh[b] = t2000;
        g_K[b] = cnt2000 < PRE ? (int)cnt2000 : PRE;
    }
    // output init: zero boxes+scores, batch indices
    for (int t = threadIdx.x; t < BATCH * POST * 5; t += 256) out[t] = 0.0f;
    for (int t = threadIdx.x; t < BATCH * POST; t += 256)
        out[BATCH * POST * 5 + t] = (float)(t / POST);
}

// ---------------- warp-aggregated append ----------------
__device__ __forceinline__ void wappend(bool cand, unsigned long long key,
                                        int* counter,
                                        unsigned long long* buf, int cap,
                                        int lane) {
    unsigned ballot = __ballot_sync(FULL, cand);
    if (cand) {
        int leader = __ffs(ballot) - 1;
        int rank = __popc(ballot & ((1u << lane) - 1u));
        int pos = 0;
        if (lane == leader) pos = atomicAdd(counter, __popc(ballot));
        pos = __shfl_sync(ballot, pos, leader) + rank;
        if (pos < cap) buf[pos] = key;
    }
}

// ---------------- K3: 4-wide gather of both lists + hist clear --------------
__global__ void __launch_bounds__(256) k_gather(const float* __restrict__ score) {
    int b = blockIdx.y;
    if (blockIdx.x < 16)                        // 16*256 == NBIN
        g_hist[b][blockIdx.x * 256 + threadIdx.x] = 0u;
    int tid4 = blockIdx.x * 256 + threadIdx.x;  // 144*256 == NA/4
    int lane = threadIdx.x & 31;
    float4 s4 = ((const float4*)(score + (size_t)b * NA))[tid4];
    unsigned vb = g_validb[b][tid4];
    int thr2000 = g_thresh[b], thr512 = g_thr512[b];
    float sv[4] = {s4.x, s4.y, s4.z, s4.w};
#pragma unroll
    for (int k = 0; k < 4; k++) {
        int i = tid4 * 4 + k;
        bool valid = (vb >> k) & 1u;
        int bin = score_bin(sv[k]);
        unsigned u = __float_as_uint(sv[k]) | 0x80000000u;   // s >= 0
        unsigned long long key = ((unsigned long long)u << 32) | (unsigned)(~i);
        wappend(valid && bin >= thr2000, key, &g_count[b], g_ckey[b], SLOTS, lane);
        wappend(valid && bin >= thr512,  key, &g_c512[b], g_key512[b], CAP512, lane);
    }
}

// ---------------- K4: 1024-wide bitonic (desc) on top-512 list + decode -----
__global__ void __launch_bounds__(512) k_sort512(const float* __restrict__ anchor,
                          const float* __restrict__ reg) {
    __shared__ unsigned long long sm[CAP512];
    int b = blockIdx.x;
    int t = threadIdx.x;                        // 512 threads
    int Craw = g_c512[b];
    int C = Craw > CAP512 ? CAP512 : Craw;
    sm[t]       = (t < C)       ? g_key512[b][t]       : 0ULL;
    sm[t + 512] = (t + 512 < C) ? g_key512[b][t + 512] : 0ULL;
    for (int k = 2; k <= CAP512; k <<= 1) {
        for (int j = k >> 1; j > 0; j >>= 1) {
            __syncthreads();
            int i = ((t & ~(j - 1)) << 1) | (t & (j - 1));   // bit j of i == 0
            int p = i | j;
            unsigned long long a = sm[i], c = sm[p];
            bool takeMax = (i & k) == 0;        // descending final order
            if ((a < c) == takeMax) { sm[i] = c; sm[p] = a; }
        }
    }
    __syncthreads();
    if (t == 0) { g_K512[b] = Craw; g_c512[b] = 0; }   // reset invariant
    int K5 = C < 512 ? C : 512;
    const float4* A = (const float4*)anchor + (size_t)b * NA;
    const float4* R = (const float4*)reg + (size_t)b * NA;
    float4 bx = make_float4(0.f, 0.f, 0.f, 0.f);
    float sc = 0.f;
    if (t < K5) {
        unsigned long long key = sm[t];
        int i = ~((unsigned)key);
        bool valid;
        decode_box(A[i], R[i], bx, valid);      // exact fp64 for winners
        sc = __uint_as_float(((unsigned)(key >> 32)) & 0x7fffffffu);
    }
    g_box[b][t] = bx;
    g_sscore[b][t] = sc;
}

// ---------------- shared IoU test ----------------
__device__ __forceinline__ bool iou_over(float4 ib, float ia, float4 jb) {
    float ty = fmaxf(ib.x, jb.x);
    float by = fminf(ib.z, jb.z);
    float lx = fmaxf(ib.y, jb.y);
    float rx = fminf(ib.w, jb.w);
    float inter = fmaxf(by - ty, 0.f) * fmaxf(rx - lx, 0.f);
    float ja = (jb.z - jb.x) * (jb.w - jb.y);
    // prefilter: iou>0.7 => 1.7*inter > 0.7*(ia+ja); 2e-4 margin
    if (inter * 1.7002f > 0.69993f * (ia + ja)) {
        float iou = inter / (ia + ja - inter + 1e-9f);   // exact IEEE
        return iou > NMS_THR;
    }
    return false;
}

// ---------------- K5: 512-prefix suppression bitmask (128 blocks) -----------
__global__ void __launch_bounds__(256) k_mask512() {
    int b = blockIdx.y;
    int bi = blockIdx.x;                        // 16 blocks of 32 i's
    int lane = threadIdx.x & 31;
    int w = threadIdx.x >> 5;                   // 8 warps = words 0..7
    int i = bi * 32 + lane;                     // < 512
    float4 ib = g_box[b][i];
    float ia = (ib.z - ib.x) * (ib.w - ib.y);
    if (w * 64 + 63 <= bi * 32) {               // whole word below diagonal
        g_mask512[b][i][w] = 0ULL;
        return;
    }
    unsigned long long bits = 0ULL;
    for (int k = 0; k < 64; k++) {
        int j = w * 64 + k;                     // warp-uniform j, < 512
        float4 jb = __ldg(&g_box[b][j]);
        if (j > i && iou_over(ib, ia, jb)) bits |= (1ULL << k);
    }
    g_mask512[b][i][w] = bits;
}

// ---------------- K6: 512-prefix scan; emit output if decisive --------------
__global__ void __launch_bounds__(32) k_scan512(float* out) {
    int b = blockIdx.x;
    int lane = threadIdx.x;                     // 32 threads; words on lanes<8
    int Kb = g_K[b];
    int Craw = g_K512[b];
    int C = Craw > CAP512 ? CAP512 : Craw;
    int K5 = C < 512 ? C : 512;

    unsigned long long removed;
    if (lane < 8) {
        int lo = lane * 64;
        if (K5 <= lo) removed = ~0ULL;
        else if (K5 >= lo + 64) removed = 0ULL;
        else removed = (~0ULL) << (K5 - lo);
    } else removed = ~0ULL;

    unsigned long long cur[16], nxt[16];
#pragma unroll
    for (int d = 0; d < 16; d++)
        cur[d] = (lane < 8 && d < K5) ? g_mask512[b][d][lane] : 0ULL;

    for (int ib = 0; ib < 512; ib += 16) {
        if (ib >= K5) break;
#pragma unroll
        for (int d = 0; d < 16; d++) {
            int pf = ib + 16 + d;
            nxt[d] = (lane < 8 && pf < K5) ? g_mask512[b][pf][lane] : 0ULL;
        }
        int w = ib >> 6;                        // uniform (16 | 64), < 8
        unsigned dec = 0;
        if (lane == w) {
            unsigned long long rw = removed;
#pragma unroll
            for (int d = 0; d < 16; d++) {
                int i = ib + d;
                if (i < K5 && !((rw >> (i & 63)) & 1ULL)) {
                    dec |= 1u << d;
                    rw |= cur[d];
                }
            }
        }
        dec = __shfl_sync(FULL, dec, w);
#pragma unroll
        for (int d = 0; d < 16; d++)
            if (dec & (1u << d)) removed |= cur[d];
#pragma unroll
        for (int d = 0; d < 16; d++) cur[d] = nxt[d];
    }

    unsigned long long kept = ~removed;         // lanes>=8 contribute 0
    int cnt = __popcll(kept);
    int total = cnt;
#pragma unroll
    for (int off = 16; off >= 1; off >>= 1)
        total += __shfl_xor_sync(FULL, total, off);

    // prefix decides iff it yields >=POST keeps, or it IS the whole list
    bool done = ((total >= POST) || (Kb <= 512)) && (Craw <= CAP512);
    if (lane == 0) g_done[b] = done ? 1 : 0;
    if (!done) return;

    int incl = cnt;
#pragma unroll
    for (int off = 1; off < 32; off <<= 1) {
        int v = __shfl_up_sync(FULL, incl, off);
        if (lane >= off) incl += v;
    }
    int base = incl - cnt;

    unsigned long long m = kept;
    while (m) {
        int t = __ffsll(m) - 1;
        m &= m - 1ULL;
        if (base < POST) {
            int slot = lane * 64 + t;           // < 512
            *(float4*)(out + ((size_t)b * POST + base) * 4) = g_box[b][slot];
            out[BATCH * POST * 4 + b * POST + base] = g_sscore[b][slot];
        }
        base++;
    }
}

// ---------------- K7: full fallback (sort+mask+scan in-block, gated) --------
// __launch_bounds__(1024, 1) caps regs at 64/thread so the launch always
// fits; the scan phase may spill to local — acceptable on this cold path.
__global__ void __launch_bounds__(1024, 1) k_fallback(
                           const float* __restrict__ anchor,
                           const float* __restrict__ reg, float* out) {
    __shared__ unsigned long long kk[SLOTS];    // 16 KB
    int b = blockIdx.x;
    int tid = threadIdx.x;                      // 1024 threads
    int C = g_count[b];
    __syncthreads();                            // all reads before reset
    if (tid == 0) g_count[b] = 0;               // restore invariant ALWAYS
    if (g_done[b]) return;                      // prefix path already emitted
    if (C > SLOTS) C = SLOTS;
#pragma unroll
    for (int e = 0; e < 2; e++) {
        int i = e * 1024 + tid;
        kk[i] = (i < C) ? g_ckey[b][i] : 0ULL;  // real keys have top bit set
    }
    for (int k = 2; k <= SLOTS; k <<= 1) {
        for (int j = k >> 1; j > 0; j >>= 1) {
            __syncthreads();
#pragma unroll
            for (int e = 0; e < 2; e++) {
                int i = e * 1024 + tid;
                int ixj = i ^ j;
                if (ixj > i) {
                    unsigned long long a = kk[i], c = kk[ixj];
                    bool sw = ((i & k) == 0) ? (a < c) : (a > c);
                    if (sw) { kk[i] = c; kk[ixj] = a; }
                }
            }
        }
    }
    __syncthreads();
    int Kb = (C < PRE) ? C : PRE;
    const float4* A = (const float4*)anchor + (size_t)b * NA;
    const float4* R = (const float4*)reg + (size_t)b * NA;
#pragma unroll
    for (int e = 0; e < 2; e++) {
        int p = e * 1024 + tid;
        float4 bx = make_float4(0.f, 0.f, 0.f, 0.f);
        float sc = 0.f;
        if (p < Kb) {
            unsigned long long key = kk[p];
            int i = ~((unsigned)key);
            bool valid;
            decode_box(A[i], R[i], bx, valid);
            sc = __uint_as_float(((unsigned)(key >> 32)) & 0x7fffffffu);
        }
        g_box[b][p] = bx;
        g_sscore[b][p] = sc;
    }
    __syncthreads();                            // g_box visible block-wide
    // full 2000x2048 suppression mask (slow; correctness-only path)
    for (int idx = tid; idx < PRE * 32; idx += 1024) {
        int i = idx >> 5, w = idx & 31;
        if (i >= Kb) continue;                  // rows >= Kb never read
        if (w * 64 + 63 <= i) continue;         // stays 0 (never written by anyone)
        float4 ib = g_box[b][i];
        float ia = (ib.z - ib.x) * (ib.w - ib.y);
        unsigned long long bits = 0ULL;
        for (int k = 0; k < 64; k++) {
            int j = w * 64 + k;
            float4 jb = g_box[b][j];
            if (j > i && iou_over(ib, ia, jb)) bits |= (1ULL << k);
        }
        g_mask[b][i][w] = bits;
    }
    __syncthreads();                            // mask visible block-wide
    if (tid >= 32) return;
    // warp 0: full greedy scan + emit
    int lane = tid;
    unsigned long long removed;
    {
        int lo = lane * 64;
        if (Kb <= lo) removed = ~0ULL;
        else if (Kb >= lo + 64) removed = 0ULL;
        else removed = (~0ULL) << (Kb - lo);
    }
    unsigned long long cur[16], nxt[16];
#pragma unroll
    for (int d = 0; d < 16; d++) cur[d] = (d < Kb) ? g_mask[b][d][lane] : 0ULL;
    for (int ibase = 0; ibase < PRE; ibase += 16) {
        if (ibase >= Kb) break;
#pragma unroll
        for (int d = 0; d < 16; d++) {
            int pf = ibase + 16 + d;
            nxt[d] = (pf < Kb) ? g_mask[b][pf][lane] : 0ULL;
        }
        int w = ibase >> 6;                     // uniform (16 | 64)
        unsigned dec = 0;
        if (lane == w) {
            unsigned long long rw = removed;
#pragma unroll
            for (int d = 0; d < 16; d++) {
                int i = ibase + d;
                if (i < Kb && !((rw >> (i & 63)) & 1ULL)) {
                    dec |= 1u << d;
                    rw |= cur[d];
                }
            }
        }
        dec = __shfl_sync(FULL, dec, w);
#pragma unroll
        for (int d = 0; d < 16; d++)
            if (dec & (1u << d)) removed |= cur[d];
#pragma unroll
        for (int d = 0; d < 16; d++) cur[d] = nxt[d];
    }
    unsigned long long kept = ~removed;
    int cnt = __popcll(kept);
    int incl = cnt;
#pragma unroll
    for (int off = 1; off < 32; off <<= 1) {
        int v = __shfl_up_sync(FULL, incl, off);
        if (lane >= off) incl += v;
    }
    int base = incl - cnt;
    unsigned long long m = kept;
    while (m) {
        int t = __ffsll(m) - 1;
        m &= m - 1ULL;
        if (base < POST) {
            int slot = lane * 64 + t;
            *(float4*)(out + ((size_t)b * POST + base) * 4) = g_box[b][slot];
            out[BATCH * POST * 4 + b * POST + base] = g_sscore[b][slot];
        }
        base++;
    }
}

// ---------------- launch ----------------
extern "C" void kernel_launch(void* const* d_in, const int* in_sizes, int n_in,
                              void* d_out, int out_size) {
    const float* anchor = (const float*)d_in[0];
    const float* breg   = (const float*)d_in[1];
    const float* score  = (const float*)d_in[2];
    float* out = (float*)d_out;

    k_hist<<<dim3(144, BATCH), 256>>>(anchor, breg, score);
    k_thresh<<<1, 256>>>(out);
    k_gather<<<dim3(144, BATCH), 256>>>(score);
    k_sort512<<<BATCH, 512>>>(anchor, breg);
    k_mask512<<<dim3(16, BATCH), 256>>>();
    k_scan512<<<BATCH, 32>>>(out);
    k_fallback<<<BATCH, 1024>>>(anchor, breg, out);
}

// round 15
// speedup vs baseline: 1.1680x; 1.0258x over previous
#include <cuda_runtime.h>
#include <math.h>

#define BATCH 8
#define NA 147456
#define PRE 2000
#define POST 300
#define NBIN 4096
#define SLOTS 2048
#define CAP512 1024
#define NMS_THR 0.7f
#define IMG 1024.0f
#define ABASE 16.0f
#define FULL 0xffffffffu

// ---------------- scratch (zero-init at load; kernels restore invariants) ---
__device__ unsigned int       g_hist[BATCH][NBIN];
__device__ unsigned char      g_validb[BATCH][NA / 4];
__device__ int                g_c512[BATCH];
__device__ int                g_count[BATCH];
__device__ int                g_K[BATCH];      // min(PRE, cnt@thr2000)
__device__ int                g_K512[BATCH];   // raw count @thr512
__device__ unsigned long long g_key512[BATCH][CAP512];
__device__ unsigned long long g_ckey[BATCH][SLOTS];
__device__ float4             g_box[BATCH][SLOTS];
__device__ float              g_sscore[BATCH][SLOTS];
__device__ unsigned long long g_mask512[BATCH][512][8];
__device__ unsigned long long g_mask[BATCH][PRE][32];

// ---------------- exact decode (fp64 exp — reference decision path) ---------
__device__ __forceinline__ void decode_box(float4 a, float4 r,
                                           float4& box, bool& valid) {
    float ah  = a.z - a.x;
    float aw  = a.w - a.y;
    float acy = a.x + 0.5f * ah;
    float acx = a.y + 0.5f * aw;
    float cy  = r.x * ah + acy;
    float cx  = r.y * aw + acx;
    float hh  = (float)exp((double)r.z) * ah;
    float ww  = (float)exp((double)r.w) * aw;
    float y1 = fminf(fmaxf(cy - 0.5f * hh, 0.0f), IMG);
    float x1 = fminf(fmaxf(cx - 0.5f * ww, 0.0f), IMG);
    float y2 = fminf(fmaxf(cy + 0.5f * hh, 0.0f), IMG);
    float x2 = fminf(fmaxf(cx + 0.5f * ww, 0.0f), IMG);
    box = make_float4(y1, x1, y2, x2);
    valid = ((y2 - y1) >= ABASE) && ((x2 - x1) >= ABASE);
}

// fast validity: fp32 __expf with margin; falls back to exact fp64 on boundary
__device__ __forceinline__ bool decode_valid_fast(float4 a, float4 r) {
    float ah  = a.z - a.x;
    float aw  = a.w - a.y;
    float acy = a.x + 0.5f * ah;
    float acx = a.y + 0.5f * aw;
    float cy  = r.x * ah + acy;
    float cx  = r.y * aw + acx;
    float hh  = __expf(r.z) * ah;
    float ww  = __expf(r.w) * aw;
    float y1 = fminf(fmaxf(cy - 0.5f * hh, 0.0f), IMG);
    float x1 = fminf(fmaxf(cx - 0.5f * ww, 0.0f), IMG);
    float y2 = fminf(fmaxf(cy + 0.5f * hh, 0.0f), IMG);
    float x2 = fminf(fmaxf(cx + 0.5f * ww, 0.0f), IMG);
    float dh = (y2 - y1) - ABASE;
    float dw = (x2 - x1) - ABASE;
    float mh = 1e-3f + 1e-5f * fabsf(hh);   // >> worst fast-vs-exact divergence
    float mw = 1e-3f + 1e-5f * fabsf(ww);
    if (fabsf(dh) >= mh && fabsf(dw) >= mw)
        return (dh > 0.0f) && (dw > 0.0f);
    float4 box; bool valid;                 // boundary: exact path
    decode_box(a, r, box, valid);
    return valid;
}

__device__ __forceinline__ int score_bin(float s) {
    int b = (int)(s * 4096.0f);
    return b > 4095 ? 4095 : (b < 0 ? 0 : b);
}

// warp 0 computes (thr512, thr2000, K) for batch b from g_hist. ~2-3 strips
// on typical data (each 32-bin strip holds ~1100 valid anchors).
__device__ __forceinline__ void compute_thresholds(int b, int lane,
                                                   int& t512, int& t2000,
                                                   int& Kb) {
    unsigned acc = 0, cnt2000 = 0;
    bool f512 = false, f2000 = false;
    t512 = 0; t2000 = 0;
    for (int s = 127; s >= 0 && !f2000; --s) {
        unsigned r = g_hist[b][s * 32 + lane];
#pragma unroll
        for (int off = 1; off < 32; off <<= 1) {
            unsigned t = __shfl_down_sync(FULL, r, off);
            if (lane < 32 - off) r += t;        // suffix sum within strip
        }
        unsigned tot = __shfl_sync(FULL, r, 0);
        if (!f512 && acc + tot >= 512) {
            unsigned bal = __ballot_sync(FULL, acc + r >= 512);
            t512 = s * 32 + (31 - __clz(bal));
            f512 = true;
        }
        if (acc + tot >= PRE) {
            unsigned bal = __ballot_sync(FULL, acc + r >= PRE);
            int L = 31 - __clz(bal);
            t2000 = s * 32 + L;
            cnt2000 = acc + __shfl_sync(FULL, r, L);
            f2000 = true;
        }
        acc += tot;
    }
    if (!f2000) cnt2000 = acc;                  // fewer than PRE valid total
    Kb = cnt2000 < PRE ? (int)cnt2000 : PRE;
}

// ---------------- K1: 4-wide validity bytes + histogram (+out init) ---------
__global__ void __launch_bounds__(256) k_hist(const float* __restrict__ anchor,
                       const float* __restrict__ reg,
                       const float* __restrict__ score, float* out) {
    __shared__ unsigned int sh[NBIN];
    int b = blockIdx.y;
    for (int i = threadIdx.x; i < NBIN; i += 256) sh[i] = 0;
    __syncthreads();
    const float4* A = (const float4*)anchor + (size_t)b * NA;
    const float4* R = (const float4*)reg + (size_t)b * NA;
    int tid4 = blockIdx.x * 256 + threadIdx.x;  // 144*256 == NA/4 exactly
    float4 s4 = ((const float4*)(score + (size_t)b * NA))[tid4];
    float4 a[4], r[4];
#pragma unroll
    for (int k = 0; k < 4; k++) {               // 9 LDG.128 issued up front
        a[k] = A[tid4 * 4 + k];
        r[k] = R[tid4 * 4 + k];
    }
    unsigned bits = 0;
#pragma unroll
    for (int k = 0; k < 4; k++)
        if (decode_valid_fast(a[k], r[k])) bits |= 1u << k;
    g_validb[b][tid4] = (unsigned char)bits;
    float sv[4] = {s4.x, s4.y, s4.z, s4.w};
#pragma unroll
    for (int k = 0; k < 4; k++)
        if ((bits >> k) & 1u) atomicAdd(&sh[score_bin(sv[k])], 1u);
    __syncthreads();
    for (int i = threadIdx.x; i < NBIN; i += 256)
        if (sh[i]) atomicAdd(&g_hist[b][i], sh[i]);
    // block (0,0): output init (independent of everything in this launch)
    if (blockIdx.x == 0 && b == 0) {
        for (int t = threadIdx.x; t < BATCH * POST * 5; t += 256) out[t] = 0.0f;
        for (int t = threadIdx.x; t < BATCH * POST; t += 256)
            out[BATCH * POST * 5 + t] = (float)(t / POST);
    }
}

// ---------------- warp-aggregated append ----------------
__device__ __forceinline__ void wappend(bool cand, unsigned long long key,
                                        int* counter,
                                        unsigned long long* buf, int cap,
                                        int lane) {
    unsigned ballot = __ballot_sync(FULL, cand);
    if (cand) {
        int leader = __ffs(ballot) - 1;
        int rank = __popc(ballot & ((1u << lane) - 1u));
        int pos = 0;
        if (lane == leader) pos = atomicAdd(counter, __popc(ballot));
        pos = __shfl_sync(ballot, pos, leader) + rank;
        if (pos < cap) buf[pos] = key;
    }
}

// ---------------- K2: per-block thresholds + 4-wide dual gather -------------
__global__ void __launch_bounds__(256) k_gather(const float* __restrict__ score) {
    __shared__ int s_thr512, s_thr2000;
    int b = blockIdx.y;
    if (threadIdx.x < 32) {                     // warp 0: redundant thresholds
        int t512, t2000, Kb;
        compute_thresholds(b, threadIdx.x, t512, t2000, Kb);
        if (threadIdx.x == 0) {
            s_thr512 = t512;
            s_thr2000 = t2000;
            if (blockIdx.x == 0) g_K[b] = Kb;   // one writer per batch
        }
    }
    __syncthreads();
    int thr2000 = s_thr2000, thr512 = s_thr512;
    int tid4 = blockIdx.x * 256 + threadIdx.x;  // 144*256 == NA/4
    int lane = threadIdx.x & 31;
    float4 s4 = ((const float4*)(score + (size_t)b * NA))[tid4];
    unsigned vb = g_validb[b][tid4];
    float sv[4] = {s4.x, s4.y, s4.z, s4.w};
#pragma unroll
    for (int k = 0; k < 4; k++) {
        int i = tid4 * 4 + k;
        bool valid = (vb >> k) & 1u;
        int bin = score_bin(sv[k]);
        unsigned u = __float_as_uint(sv[k]) | 0x80000000u;   // s >= 0
        unsigned long long key = ((unsigned long long)u << 32) | (unsigned)(~i);
        wappend(valid && bin >= thr2000, key, &g_count[b], g_ckey[b], SLOTS, lane);
        wappend(valid && bin >= thr512,  key, &g_c512[b], g_key512[b], CAP512, lane);
    }
}

// ---------------- K3: 1024-wide bitonic (desc) + decode + hist clear --------
__global__ void __launch_bounds__(512) k_sort512(const float* __restrict__ anchor,
                          const float* __restrict__ reg) {
    __shared__ unsigned long long sm[CAP512];
    int b = blockIdx.x;
    int t = threadIdx.x;                        // 512 threads
    int Craw = g_c512[b];
    int C = Craw > CAP512 ? CAP512 : Craw;
    sm[t]       = (t < C)       ? g_key512[b][t]       : 0ULL;
    sm[t + 512] = (t + 512 < C) ? g_key512[b][t + 512] : 0ULL;
    // restore hist zero-invariant (gather's threshold reads are all done)
    for (int i = t; i < NBIN; i += 512) g_hist[b][i] = 0u;
    for (int k = 2; k <= CAP512; k <<= 1) {
        for (int j = k >> 1; j > 0; j >>= 1) {
            __syncthreads();
            int i = ((t & ~(j - 1)) << 1) | (t & (j - 1));   // bit j of i == 0
            int p = i | j;
            unsigned long long a = sm[i], c = sm[p];
            bool takeMax = (i & k) == 0;        // descending final order
            if ((a < c) == takeMax) { sm[i] = c; sm[p] = a; }
        }
    }
    __syncthreads();
    if (t == 0) { g_K512[b] = Craw; g_c512[b] = 0; }   // reset invariant
    int K5 = C < 512 ? C : 512;
    const float4* A = (const float4*)anchor + (size_t)b * NA;
    const float4* R = (const float4*)reg + (size_t)b * NA;
    float4 bx = make_float4(0.f, 0.f, 0.f, 0.f);
    float sc = 0.f;
    if (t < K5) {
        unsigned long long key = sm[t];
        int i = ~((unsigned)key);
        bool valid;
        decode_box(A[i], R[i], bx, valid);      // exact fp64 for winners
        sc = __uint_as_float(((unsigned)(key >> 32)) & 0x7fffffffu);
    }
    g_box[b][t] = bx;
    g_sscore[b][t] = sc;
}

// ---------------- shared IoU test ----------------
__device__ __forceinline__ bool iou_over(float4 ib, float ia, float4 jb) {
    float ty = fmaxf(ib.x, jb.x);
    float by = fminf(ib.z, jb.z);
    float lx = fmaxf(ib.y, jb.y);
    float rx = fminf(ib.w, jb.w);
    float inter = fmaxf(by - ty, 0.f) * fmaxf(rx - lx, 0.f);
    float ja = (jb.z - jb.x) * (jb.w - jb.y);
    // prefilter: iou>0.7 => 1.7*inter > 0.7*(ia+ja); 2e-4 margin
    if (inter * 1.7002f > 0.69993f * (ia + ja)) {
        float iou = inter / (ia + ja - inter + 1e-9f);   // exact IEEE
        return iou > NMS_THR;
    }
    return false;
}

// ---------------- K4: 512-prefix suppression bitmask (128 blocks) -----------
__global__ void __launch_bounds__(256) k_mask512() {
    int b = blockIdx.y;
    int bi = blockIdx.x;                        // 16 blocks of 32 i's
    int lane = threadIdx.x & 31;
    int w = threadIdx.x >> 5;                   // 8 warps = words 0..7
    int i = bi * 32 + lane;                     // < 512
    float4 ib = g_box[b][i];
    float ia = (ib.z - ib.x) * (ib.w - ib.y);
    if (w * 64 + 63 <= bi * 32) {               // whole word below diagonal
        g_mask512[b][i][w] = 0ULL;
        return;
    }
    unsigned long long bits = 0ULL;
    for (int k = 0; k < 64; k++) {
        int j = w * 64 + k;                     // warp-uniform j, < 512
        float4 jb = __ldg(&g_box[b][j]);
        if (j > i && iou_over(ib, ia, jb)) bits |= (1ULL << k);
    }
    g_mask512[b][i][w] = bits;
}

// ---------------- K5: prefix scan + emit; gated full fallback ---------------
// 512 threads => 128-reg budget: warp-0 scan arrays stay in registers.
__global__ void __launch_bounds__(512, 1) k_final(
                           const float* __restrict__ anchor,
                           const float* __restrict__ reg, float* out) {
    __shared__ unsigned long long kk[SLOTS];    // 16 KB
    __shared__ int s_done;
    int b = blockIdx.x;
    int tid = threadIdx.x;                      // 512 threads
    int C2000 = g_count[b];
    __syncthreads();                            // reads before reset
    if (tid == 0) g_count[b] = 0;               // restore invariant ALWAYS

    // ---- warp 0: greedy scan over 512 prefix; emit if decisive ----
    if (tid < 32) {
        int lane = tid;
        int Kb = g_K[b];
        int Craw = g_K512[b];
        int C = Craw > CAP512 ? CAP512 : Craw;
        int K5 = C < 512 ? C : 512;

        unsigned long long removed;
        if (lane < 8) {
            int lo = lane * 64;
            if (K5 <= lo) removed = ~0ULL;
            else if (K5 >= lo + 64) removed = 0ULL;
            else removed = (~0ULL) << (K5 - lo);
        } else removed = ~0ULL;

        unsigned long long cur[16], nxt[16];
#pragma unroll
        for (int d = 0; d < 16; d++)
            cur[d] = (lane < 8 && d < K5) ? g_mask512[b][d][lane] : 0ULL;

        for (int ibase = 0; ibase < 512; ibase += 16) {
            if (ibase >= K5) break;
#pragma unroll
            for (int d = 0; d < 16; d++) {
                int pf = ibase + 16 + d;
                nxt[d] = (lane < 8 && pf < K5) ? g_mask512[b][pf][lane] : 0ULL;
            }
            int w = ibase >> 6;                 // uniform (16 | 64), < 8
            unsigned dec = 0;
            if (lane == w) {
                unsigned long long rw = removed;
#pragma unroll
                for (int d = 0; d < 16; d++) {
                    int ii = ibase + d;
                    if (ii < K5 && !((rw >> (ii & 63)) & 1ULL)) {
                        dec |= 1u << d;
                        rw |= cur[d];
                    }
                }
            }
            dec = __shfl_sync(FULL, dec, w);
#pragma unroll
            for (int d = 0; d < 16; d++)
                if (dec & (1u << d)) removed |= cur[d];
#pragma unroll
            for (int d = 0; d < 16; d++) cur[d] = nxt[d];
        }

        unsigned long long kept = ~removed;     // lanes>=8 contribute 0
        int cnt = __popcll(kept);
        int total = cnt;
#pragma unroll
        for (int off = 16; off >= 1; off >>= 1)
            total += __shfl_xor_sync(FULL, total, off);

        bool done = ((total >= POST) || (Kb <= 512)) && (Craw <= CAP512);
        if (lane == 0) s_done = done ? 1 : 0;
        if (done) {
            int incl = cnt;
#pragma unroll
            for (int off = 1; off < 32; off <<= 1) {
                int v = __shfl_up_sync(FULL, incl, off);
                if (lane >= off) incl += v;
            }
            int base = incl - cnt;
            unsigned long long m = kept;
            while (m) {
                int t = __ffsll(m) - 1;
                m &= m - 1ULL;
                if (base < POST) {
                    int slot = lane * 64 + t;   // < 512
                    *(float4*)(out + ((size_t)b * POST + base) * 4) = g_box[b][slot];
                    out[BATCH * POST * 4 + b * POST + base] = g_sscore[b][slot];
                }
                base++;
            }
        }
    }
    __syncthreads();
    if (s_done) return;

    // ================= full fallback (cold, correctness-only) ===============
    int C = C2000 > SLOTS ? SLOTS : C2000;
#pragma unroll
    for (int e = 0; e < 4; e++) {
        int i = e * 512 + tid;
        kk[i] = (i < C) ? g_ckey[b][i] : 0ULL;  // real keys have top bit set
    }
    for (int k = 2; k <= SLOTS; k <<= 1) {
        for (int j = k >> 1; j > 0; j >>= 1) {
            __syncthreads();
#pragma unroll
            for (int e = 0; e < 4; e++) {
                int i = e * 512 + tid;
                int ixj = i ^ j;
                if (ixj > i) {
                    unsigned long long a = kk[i], c = kk[ixj];
                    bool sw = ((i & k) == 0) ? (a < c) : (a > c);
                    if (sw) { kk[i] = c; kk[ixj] = a; }
                }
            }
        }
    }
    __syncthreads();
    int Kb = (C < PRE) ? C : PRE;
    const float4* A = (const float4*)anchor + (size_t)b * NA;
    const float4* R = (const float4*)reg + (size_t)b * NA;
#pragma unroll
    for (int e = 0; e < 4; e++) {
        int p = e * 512 + tid;
        float4 bx = make_float4(0.f, 0.f, 0.f, 0.f);
        float sc = 0.f;
        if (p < Kb) {
            unsigned long long key = kk[p];
            int i = ~((unsigned)key);
            bool valid;
            decode_box(A[i], R[i], bx, valid);
            sc = __uint_as_float(((unsigned)(key >> 32)) & 0x7fffffffu);
        }
        g_box[b][p] = bx;
        g_sscore[b][p] = sc;
    }
    __syncthreads();                            // g_box visible block-wide
    // full suppression mask (slow; correctness-only path)
    for (int idx = tid; idx < PRE * 32; idx += 512) {
        int i = idx >> 5, w = idx & 31;
        if (i >= Kb) continue;                  // rows >= Kb never read
        if (w * 64 + 63 <= i) continue;         // stays 0 (never written)
        float4 ib = g_box[b][i];
        float ia = (ib.z - ib.x) * (ib.w - ib.y);
        unsigned long long bits = 0ULL;
        for (int k = 0; k < 64; k++) {
            int j = w * 64 + k;
            float4 jb = g_box[b][j];
            if (j > i && iou_over(ib, ia, jb)) bits |= (1ULL << k);
        }
        g_mask[b][i][w] = bits;
    }
    __syncthreads();                            // mask visible block-wide
    if (tid >= 32) return;
    // warp 0: full greedy scan + emit
    int lane = tid;
    unsigned long long removed;
    {
        int lo = lane * 64;
        if (Kb <= lo) removed = ~0ULL;
        else if (Kb >= lo + 64) removed = 0ULL;
        else removed = (~0ULL) << (Kb - lo);
    }
    unsigned long long cur[16], nxt[16];
#pragma unroll
    for (int d = 0; d < 16; d++) cur[d] = (d < Kb) ? g_mask[b][d][lane] : 0ULL;
    for (int ibase = 0; ibase < PRE; ibase += 16) {
        if (ibase >= Kb) break;
#pragma unroll
        for (int d = 0; d < 16; d++) {
            int pf = ibase + 16 + d;
            nxt[d] = (pf < Kb) ? g_mask[b][pf][lane] : 0ULL;
        }
        int w = ibase >> 6;                     // uniform (16 | 64)
        unsigned dec = 0;
        if (lane == w) {
            unsigned long long rw = removed;
#pragma unroll
            for (int d = 0; d < 16; d++) {
                int i = ibase + d;
                if (i < Kb && !((rw >> (i & 63)) & 1ULL)) {
                    dec |= 1u << d;
                    rw |= cur[d];
                }
            }
        }
        dec = __shfl_sync(FULL, dec, w);
#pragma unroll
        for (int d = 0; d < 16; d++)
            if (dec & (1u << d)) removed |= cur[d];
#pragma unroll
        for (int d = 0; d < 16; d++) cur[d] = nxt[d];
    }
    unsigned long long kept = ~removed;
    int cnt = __popcll(kept);
    int incl = cnt;
#pragma unroll
    for (int off = 1; off < 32; off <<= 1) {
        int v = __shfl_up_sync(FULL, incl, off);
        if (lane >= off) incl += v;
    }
    int base = incl - cnt;
    unsigned long long m = kept;
    while (m) {
        int t = __ffsll(m) - 1;
        m &= m - 1ULL;
        if (base < POST) {
            int slot = lane * 64 + t;
            *(float4*)(out + ((size_t)b * POST + base) * 4) = g_box[b][slot];
            out[BATCH * POST * 4 + b * POST + base] = g_sscore[b][slot];
        }
        base++;
    }
}

// ---------------- launch ----------------
extern "C" void kernel_launch(void* const* d_in, const int* in_sizes, int n_in,
                              void* d_out, int out_size) {
    const float* anchor = (const float*)d_in[0];
    const float* breg   = (const float*)d_in[1];
    const float* score  = (const float*)d_in[2];
    float* out = (float*)d_out;

    k_hist<<<dim3(144, BATCH), 256>>>(anchor, breg, score, out);
    k_gather<<<dim3(144, BATCH), 256>>>(score);
    k_sort512<<<BATCH, 512>>>(anchor, breg);
    k_mask512<<<dim3(16, BATCH), 256>>>();
    k_final<<<BATCH, 512>>>(anchor, breg, out);
}

// round 17
// speedup vs baseline: 1.2307x; 1.0537x over previous
#include <cuda_runtime.h>
#include <math.h>

#define BATCH 8
#define NA 147456
#define PRE 2000
#define POST 300
#define NBIN 4096
#define SLOTS 2048
#define CAP512 1024
#define NMS_THR 0.7f
#define IMG 1024.0f
#define ABASE 16.0f
#define FULL 0xffffffffu

// ---------------- scratch (zero-init at load; kernels restore invariants) ---
__device__ unsigned int       g_hist[BATCH][NBIN];
__device__ unsigned char      g_validb[BATCH][NA / 4];
__device__ int                g_c512[BATCH];
__device__ int                g_count[BATCH];
__device__ int                g_K[BATCH];      // min(PRE, cnt@thr2000)
__device__ int                g_K512[BATCH];   // raw count @thr512
__device__ unsigned long long g_key512[BATCH][CAP512];
__device__ unsigned long long g_ckey[BATCH][SLOTS];
__device__ float4             g_box[BATCH][SLOTS];
__device__ float              g_sscore[BATCH][SLOTS];
__device__ unsigned long long g_mask512[BATCH][512][8];
__device__ unsigned long long g_mask[BATCH][PRE][32];

// ---------------- exact decode (fp64 exp — reference decision path) ---------
__device__ __forceinline__ void decode_box(float4 a, float4 r,
                                           float4& box, bool& valid) {
    float ah  = a.z - a.x;
    float aw  = a.w - a.y;
    float acy = a.x + 0.5f * ah;
    float acx = a.y + 0.5f * aw;
    float cy  = r.x * ah + acy;
    float cx  = r.y * aw + acx;
    float hh  = (float)exp((double)r.z) * ah;
    float ww  = (float)exp((double)r.w) * aw;
    float y1 = fminf(fmaxf(cy - 0.5f * hh, 0.0f), IMG);
    float x1 = fminf(fmaxf(cx - 0.5f * ww, 0.0f), IMG);
    float y2 = fminf(fmaxf(cy + 0.5f * hh, 0.0f), IMG);
    float x2 = fminf(fmaxf(cx + 0.5f * ww, 0.0f), IMG);
    box = make_float4(y1, x1, y2, x2);
    valid = ((y2 - y1) >= ABASE) && ((x2 - x1) >= ABASE);
}

// fast validity: fp32 __expf with margin; falls back to exact fp64 on boundary
__device__ __forceinline__ bool decode_valid_fast(float4 a, float4 r) {
    float ah  = a.z - a.x;
    float aw  = a.w - a.y;
    float acy = a.x + 0.5f * ah;
    float acx = a.y + 0.5f * aw;
    float cy  = r.x * ah + acy;
    float cx  = r.y * aw + acx;
    float hh  = __expf(r.z) * ah;
    float ww  = __expf(r.w) * aw;
    float y1 = fminf(fmaxf(cy - 0.5f * hh, 0.0f), IMG);
    float x1 = fminf(fmaxf(cx - 0.5f * ww, 0.0f), IMG);
    float y2 = fminf(fmaxf(cy + 0.5f * hh, 0.0f), IMG);
    float x2 = fminf(fmaxf(cx + 0.5f * ww, 0.0f), IMG);
    float dh = (y2 - y1) - ABASE;
    float dw = (x2 - x1) - ABASE;
    float mh = 1e-3f + 1e-5f * fabsf(hh);   // >> worst fast-vs-exact divergence
    float mw = 1e-3f + 1e-5f * fabsf(ww);
    if (fabsf(dh) >= mh && fabsf(dw) >= mw)
        return (dh > 0.0f) && (dw > 0.0f);
    float4 box; bool valid;                 // boundary: exact path
    decode_box(a, r, box, valid);
    return valid;
}

__device__ __forceinline__ int score_bin(float s) {
    int b = (int)(s * 4096.0f);
    return b > 4095 ? 4095 : (b < 0 ? 0 : b);
}

// warp 0 computes (thr512, thr2000, K) for batch b from g_hist. ~2-3 strips
// on typical data (each 32-bin strip holds ~1100 valid anchors).
__device__ __forceinline__ void compute_thresholds(int b, int lane,
                                                   int& t512, int& t2000,
                                                   int& Kb) {
    unsigned acc = 0, cnt2000 = 0;
    bool f512 = false, f2000 = false;
    t512 = 0; t2000 = 0;
    for (int s = 127; s >= 0 && !f2000; --s) {
        unsigned r = g_hist[b][s * 32 + lane];
#pragma unroll
        for (int off = 1; off < 32; off <<= 1) {
            unsigned t = __shfl_down_sync(FULL, r, off);
            if (lane < 32 - off) r += t;        // suffix sum within strip
        }
        unsigned tot = __shfl_sync(FULL, r, 0);
        if (!f512 && acc + tot >= 512) {
            unsigned bal = __ballot_sync(FULL, acc + r >= 512);
            t512 = s * 32 + (31 - __clz(bal));
            f512 = true;
        }
        if (acc + tot >= PRE) {
            unsigned bal = __ballot_sync(FULL, acc + r >= PRE);
            int L = 31 - __clz(bal);
            t2000 = s * 32 + L;
            cnt2000 = acc + __shfl_sync(FULL, r, L);
            f2000 = true;
        }
        acc += tot;
    }
    if (!f2000) cnt2000 = acc;                  // fewer than PRE valid total
    Kb = cnt2000 < PRE ? (int)cnt2000 : PRE;
}

// ---------------- K1: 4-wide validity bytes + histogram (+out init) ---------
__global__ void __launch_bounds__(256) k_hist(const float* __restrict__ anchor,
                       const float* __restrict__ reg,
                       const float* __restrict__ score, float* out) {
    __shared__ unsigned int sh[NBIN];
    int b = blockIdx.y;
    for (int i = threadIdx.x; i < NBIN; i += 256) sh[i] = 0;
    __syncthreads();
    const float4* A = (const float4*)anchor + (size_t)b * NA;
    const float4* R = (const float4*)reg + (size_t)b * NA;
    int tid4 = blockIdx.x * 256 + threadIdx.x;  // 144*256 == NA/4 exactly
    float4 s4 = ((const float4*)(score + (size_t)b * NA))[tid4];
    float4 a[4], r[4];
#pragma unroll
    for (int k = 0; k < 4; k++) {               // 9 LDG.128 issued up front
        a[k] = A[tid4 * 4 + k];
        r[k] = R[tid4 * 4 + k];
    }
    unsigned bits = 0;
#pragma unroll
    for (int k = 0; k < 4; k++)
        if (decode_valid_fast(a[k], r[k])) bits |= 1u << k;
    g_validb[b][tid4] = (unsigned char)bits;
    float sv[4] = {s4.x, s4.y, s4.z, s4.w};
#pragma unroll
    for (int k = 0; k < 4; k++)
        if ((bits >> k) & 1u) atomicAdd(&sh[score_bin(sv[k])], 1u);
    __syncthreads();
    for (int i = threadIdx.x; i < NBIN; i += 256)
        if (sh[i]) atomicAdd(&g_hist[b][i], sh[i]);
    // block (0,0): output init (independent of everything in this launch)
    if (blockIdx.x == 0 && b == 0) {
        for (int t = threadIdx.x; t < BATCH * POST * 5; t += 256) out[t] = 0.0f;
        for (int t = threadIdx.x; t < BATCH * POST; t += 256)
            out[BATCH * POST * 5 + t] = (float)(t / POST);
    }
}

// ---------------- warp-aggregated append ----------------
__device__ __forceinline__ void wappend(bool cand, unsigned long long key,
                                        int* counter,
                                        unsigned long long* buf, int cap,
                                        int lane) {
    unsigned ballot = __ballot_sync(FULL, cand);
    if (cand) {
        int leader = __ffs(ballot) - 1;
        int rank = __popc(ballot & ((1u << lane) - 1u));
        int pos = 0;
        if (lane == leader) pos = atomicAdd(counter, __popc(ballot));
        pos = __shfl_sync(ballot, pos, leader) + rank;
        if (pos < cap) buf[pos] = key;
    }
}

// ---------------- K2: per-block thresholds + 4-wide dual gather -------------
__global__ void __launch_bounds__(256) k_gather(const float* __restrict__ score) {
    __shared__ int s_thr512, s_thr2000;
    int b = blockIdx.y;
    if (threadIdx.x < 32) {                     // warp 0: redundant thresholds
        int t512, t2000, Kb;
        compute_thresholds(b, threadIdx.x, t512, t2000, Kb);
        if (threadIdx.x == 0) {
            s_thr512 = t512;
            s_thr2000 = t2000;
            if (blockIdx.x == 0) g_K[b] = Kb;   // one writer per batch
        }
    }
    __syncthreads();
    int thr2000 = s_thr2000, thr512 = s_thr512;
    int tid4 = blockIdx.x * 256 + threadIdx.x;  // 144*256 == NA/4
    int lane = threadIdx.x & 31;
    float4 s4 = ((const float4*)(score + (size_t)b * NA))[tid4];
    unsigned vb = g_validb[b][tid4];
    float sv[4] = {s4.x, s4.y, s4.z, s4.w};
#pragma unroll
    for (int k = 0; k < 4; k++) {
        int i = tid4 * 4 + k;
        bool valid = (vb >> k) & 1u;
        int bin = score_bin(sv[k]);
        unsigned u = __float_as_uint(sv[k]) | 0x80000000u;   // s >= 0
        unsigned long long key = ((unsigned long long)u << 32) | (unsigned)(~i);
        wappend(valid && bin >= thr2000, key, &g_count[b], g_ckey[b], SLOTS, lane);
        wappend(valid && bin >= thr512,  key, &g_c512[b], g_key512[b], CAP512, lane);
    }
}

// ---------------- K3: 1024-wide bitonic (desc) + decode + hist clear --------
__global__ void __launch_bounds__(512) k_sort512(const float* __restrict__ anchor,
                          const float* __restrict__ reg) {
    __shared__ unsigned long long sm[CAP512];
    int b = blockIdx.x;
    int t = threadIdx.x;                        // 512 threads
    int Craw = g_c512[b];
    int C = Craw > CAP512 ? CAP512 : Craw;
    sm[t]       = (t < C)       ? g_key512[b][t]       : 0ULL;
    sm[t + 512] = (t + 512 < C) ? g_key512[b][t + 512] : 0ULL;
    // restore hist zero-invariant (gather's threshold reads are all done)
    for (int i = t; i < NBIN; i += 512) g_hist[b][i] = 0u;
    for (int k = 2; k <= CAP512; k <<= 1) {
        for (int j = k >> 1; j > 0; j >>= 1) {
            __syncthreads();
            int i = ((t & ~(j - 1)) << 1) | (t & (j - 1));   // bit j of i == 0
            int p = i | j;
            unsigned long long a = sm[i], c = sm[p];
            bool takeMax = (i & k) == 0;        // descending final order
            if ((a < c) == takeMax) { sm[i] = c; sm[p] = a; }
        }
    }
    __syncthreads();
    if (t == 0) { g_K512[b] = Craw; g_c512[b] = 0; }   // reset invariant
    int K5 = C < 512 ? C : 512;
    const float4* A = (const float4*)anchor + (size_t)b * NA;
    const float4* R = (const float4*)reg + (size_t)b * NA;
    float4 bx = make_float4(0.f, 0.f, 0.f, 0.f);
    float sc = 0.f;
    if (t < K5) {
        unsigned long long key = sm[t];
        int i = ~((unsigned)key);
        bool valid;
        decode_box(A[i], R[i], bx, valid);      // exact fp64 for winners
        sc = __uint_as_float(((unsigned)(key >> 32)) & 0x7fffffffu);
    }
    g_box[b][t] = bx;
    g_sscore[b][t] = sc;
}

// ---------------- shared IoU test ----------------
__device__ __forceinline__ bool iou_over(float4 ib, float ia, float4 jb) {
    float ty = fmaxf(ib.x, jb.x);
    float by = fminf(ib.z, jb.z);
    float lx = fmaxf(ib.y, jb.y);
    float rx = fminf(ib.w, jb.w);
    float inter = fmaxf(by - ty, 0.f) * fmaxf(rx - lx, 0.f);
    float ja = (jb.z - jb.x) * (jb.w - jb.y);
    // prefilter: iou>0.7 => 1.7*inter > 0.7*(ia+ja); 2e-4 margin
    if (inter * 1.7002f > 0.69993f * (ia + ja)) {
        float iou = inter / (ia + ja - inter + 1e-9f);   // exact IEEE
        return iou > NMS_THR;
    }
    return false;
}

// ---------------- K4: 512-prefix mask, j-boxes staged in smem ---------------
__global__ void __launch_bounds__(256) k_mask512() {
    __shared__ float4 sb[512];                  // 8 KB: all 512 boxes
    int b = blockIdx.y;
    int bi = blockIdx.x;                        // 16 blocks of 32 i's
    for (int j = threadIdx.x; j < 512; j += 256) sb[j] = g_box[b][j];
    __syncthreads();
    int lane = threadIdx.x & 31;
    int w = threadIdx.x >> 5;                   // 8 warps = words 0..7
    int i = bi * 32 + lane;                     // < 512
    float4 ib = sb[i];
    float ia = (ib.z - ib.x) * (ib.w - ib.y);
    if (w * 64 + 63 <= bi * 32) {               // whole word below diagonal
        g_mask512[b][i][w] = 0ULL;
        return;
    }
    unsigned long long bits = 0ULL;
#pragma unroll 4
    for (int k = 0; k < 64; k++) {
        int j = w * 64 + k;                     // warp-uniform -> LDS broadcast
        float4 jb = sb[j];
        if (j > i && iou_over(ib, ia, jb)) bits |= (1ULL << k);
    }
    g_mask512[b][i][w] = bits;
}

// ---------------- K5: prefix scan + emit; gated full fallback ---------------
// 512 threads => 128-reg budget: warp-0 scan arrays stay in registers.
__global__ void __launch_bounds__(512, 1) k_final(
                           const float* __restrict__ anchor,
                           const float* __restrict__ reg, float* out) {
    __shared__ unsigned long long kk[SLOTS];    // 16 KB
    __shared__ int s_done;
    int b = blockIdx.x;
    int tid = threadIdx.x;                      // 512 threads
    int C2000 = g_count[b];
    __syncthreads();                            // reads before reset
    if (tid == 0) g_count[b] = 0;               // restore invariant ALWAYS

    // ---- warp 0: greedy scan over 512 prefix; emit if decisive ----
    if (tid < 32) {
        int lane = tid;
        int Kb = g_K[b];
        int Craw = g_K512[b];
        int C = Craw > CAP512 ? CAP512 : Craw;
        int K5 = C < 512 ? C : 512;

        unsigned long long removed;
        if (lane < 8) {
            int lo = lane * 64;
            if (K5 <= lo) removed = ~0ULL;
            else if (K5 >= lo + 64) removed = 0ULL;
            else removed = (~0ULL) << (K5 - lo);
        } else removed = ~0ULL;

        unsigned long long cur[16], nxt[16];
#pragma unroll
        for (int d = 0; d < 16; d++)
            cur[d] = (lane < 8 && d < K5) ? g_mask512[b][d][lane] : 0ULL;

        for (int ibase = 0; ibase < 512; ibase += 16) {
            if (ibase >= K5) break;
#pragma unroll
            for (int d = 0; d < 16; d++) {
                int pf = ibase + 16 + d;
                nxt[d] = (lane < 8 && pf < K5) ? g_mask512[b][pf][lane] : 0ULL;
            }
            int w = ibase >> 6;                 // uniform (16 | 64), < 8
            unsigned dec = 0;
            if (lane == w) {
                unsigned long long rw = removed;
#pragma unroll
                for (int d = 0; d < 16; d++) {
                    int ii = ibase + d;
                    if (ii < K5 && !((rw >> (ii & 63)) & 1ULL)) {
                        dec |= 1u << d;
                        rw |= cur[d];
                    }
                }
            }
            dec = __shfl_sync(FULL, dec, w);
#pragma unroll
            for (int d = 0; d < 16; d++)
                if (dec & (1u << d)) removed |= cur[d];
#pragma unroll
            for (int d = 0; d < 16; d++) cur[d] = nxt[d];
        }

        unsigned long long kept = ~removed;     // lanes>=8 contribute 0
        int cnt = __popcll(kept);
        int total = cnt;
#pragma unroll
        for (int off = 16; off >= 1; off >>= 1)
            total += __shfl_xor_sync(FULL, total, off);

        bool done = ((total >= POST) || (Kb <= 512)) && (Craw <= CAP512);
        if (lane == 0) s_done = done ? 1 : 0;
        if (done) {
            int incl = cnt;
#pragma unroll
            for (int off = 1; off < 32; off <<= 1) {
                int v = __shfl_up_sync(FULL, incl, off);
                if (lane >= off) incl += v;
            }
            int base = incl - cnt;
            unsigned long long m = kept;
            while (m) {
                int t = __ffsll(m) - 1;
                m &= m - 1ULL;
                if (base < POST) {
                    int slot = lane * 64 + t;   // < 512
                    *(float4*)(out + ((size_t)b * POST + base) * 4) = g_box[b][slot];
                    out[BATCH * POST * 4 + b * POST + base] = g_sscore[b][slot];
                }
                base++;
            }
        }
    }
    __syncthreads();
    if (s_done) return;

    // ================= full fallback (cold, correctness-only) ===============
    int C = C2000 > SLOTS ? SLOTS : C2000;
#pragma unroll
    for (int e = 0; e < 4; e++) {
        int i = e * 512 + tid;
        kk[i] = (i < C) ? g_ckey[b][i] : 0ULL;  // real keys have top bit set
    }
    for (int k = 2; k <= SLOTS; k <<= 1) {
        for (int j = k >> 1; j > 0; j >>= 1) {
            __syncthreads();
#pragma unroll
            for (int e = 0; e < 4; e++) {
                int i = e * 512 + tid;
                int ixj = i ^ j;
                if (ixj > i) {
                    unsigned long long a = kk[i], c = kk[ixj];
                    bool sw = ((i & k) == 0) ? (a < c) : (a > c);
                    if (sw) { kk[i] = c; kk[ixj] = a; }
                }
            }
        }
    }
    __syncthreads();
    int Kb = (C < PRE) ? C : PRE;
    const float4* A = (const float4*)anchor + (size_t)b * NA;
    const float4* R = (const float4*)reg + (size_t)b * NA;
#pragma unroll
    for (int e = 0; e < 4; e++) {
        int p = e * 512 + tid;
        float4 bx = make_float4(0.f, 0.f, 0.f, 0.f);
        float sc = 0.f;
        if (p < Kb) {
            unsigned long long key = kk[p];
            int i = ~((unsigned)key);
            bool valid;
            decode_box(A[i], R[i], bx, valid);
            sc = __uint_as_float(((unsigned)(key >> 32)) & 0x7fffffffu);
        }
        g_box[b][p] = bx;
        g_sscore[b][p] = sc;
    }
    __syncthreads();                            // g_box visible block-wide
    // full suppression mask (slow; correctness-only path)
    for (int idx = tid; idx < PRE * 32; idx += 512) {
        int i = idx >> 5, w = idx & 31;
        if (i >= Kb) continue;                  // rows >= Kb never read
        if (w * 64 + 63 <= i) continue;         // stays 0 (never written)
        float4 ib = g_box[b][i];
        float ia = (ib.z - ib.x) * (ib.w - ib.y);
        unsigned long long bits = 0ULL;
        for (int k = 0; k < 64; k++) {
            int j = w * 64 + k;
            float4 jb = g_box[b][j];
            if (j > i && iou_over(ib, ia, jb)) bits |= (1ULL << k);
        }
        g_mask[b][i][w] = bits;
    }
    __syncthreads();                            // mask visible block-wide
    if (tid >= 32) return;
    // warp 0: full greedy scan + emit
    int lane = tid;
    unsigned long long removed;
    {
        int lo = lane * 64;
        if (Kb <= lo) removed = ~0ULL;
        else if (Kb >= lo + 64) removed = 0ULL;
        else removed = (~0ULL) << (Kb - lo);
    }
    unsigned long long cur[16], nxt[16];
#pragma unroll
    for (int d = 0; d < 16; d++) cur[d] = (d < Kb) ? g_mask[b][d][lane] : 0ULL;
    for (int ibase = 0; ibase < PRE; ibase += 16) {
        if (ibase >= Kb) break;
#pragma unroll
        for (int d = 0; d < 16; d++) {
            int pf = ibase + 16 + d;
            nxt[d] = (pf < Kb) ? g_mask[b][pf][lane] : 0ULL;
        }
        int w = ibase >> 6;                     // uniform (16 | 64)
        unsigned dec = 0;
        if (lane == w) {
            unsigned long long rw = removed;
#pragma unroll
            for (int d = 0; d < 16; d++) {
                int i = ibase + d;
                if (i < Kb && !((rw >> (i & 63)) & 1ULL)) {
                    dec |= 1u << d;
                    rw |= cur[d];
                }
            }
        }
        dec = __shfl_sync(FULL, dec, w);
#pragma unroll
        for (int d = 0; d < 16; d++)
            if (dec & (1u << d)) removed |= cur[d];
#pragma unroll
        for (int d = 0; d < 16; d++) cur[d] = nxt[d];
    }
    unsigned long long kept = ~removed;
    int cnt = __popcll(kept);
    int incl = cnt;
#pragma unroll
    for (int off = 1; off < 32; off <<= 1) {
        int v = __shfl_up_sync(FULL, incl, off);
        if (lane >= off) incl += v;
    }
    int base = incl - cnt;
    unsigned long long m = kept;
    while (m) {
        int t = __ffsll(m) - 1;
        m &= m - 1ULL;
        if (base < POST) {
            int slot = lane * 64 + t;
            *(float4*)(out + ((size_t)b * POST + base) * 4) = g_box[b][slot];
            out[BATCH * POST * 4 + b * POST + base] = g_sscore[b][slot];
        }
        base++;
    }
}

// ---------------- launch ----------------
extern "C" void kernel_launch(void* const* d_in, const int* in_sizes, int n_in,
                              void* d_out, int out_size) {
    const float* anchor = (const float*)d_in[0];
    const float* breg   = (const float*)d_in[1];
    const float* score  = (const float*)d_in[2];
    float* out = (float*)d_out;

    k_hist<<<dim3(144, BATCH), 256>>>(anchor, breg, score, out);
    k_gather<<<dim3(144, BATCH), 256>>>(score);
    k_sort512<<<BATCH, 512>>>(anchor, breg);
    k_mask512<<<dim3(16, BATCH), 256>>>();
    k_final<<<BATCH, 512>>>(anchor, breg, out);
}